// round 13
// baseline (speedup 1.0000x reference)
#include <cuda_runtime.h>
#include <cstdint>

// CFConv fused: B=4, N=4096, K=30 (pad 32), C=64, E=300
// R13: 512 threads (4 warps/SMSP for latency hiding; R12 occ=12.5% starved
// issue), W operands loaded from smem as ulonglong2 = pre-packed f32x2 (kills
// the pk2 mov overhead that showed as alu=17.6%). 4 nodes/iter, 128 thr/node,
// 2k x 8c register tiles, fma.rn.f32x2 core, cp.async double-buffered ef.

#define NQUADS 4096
#define GRIDSZ 148

// smem layout (floats)
#define W1_OFF   0          // [300][64]            19200
#define W2_OFF   19200      // [64][64]              4096
#define EFS_OFF  23296      // 2 bufs x [4][32][60] 15360 (pitch 15 f4)
#define HS_OFF   38656      // [4][32][68]           8704
#define REDS_OFF 47360      // [16][64]              1024
#define IDX_OFF  48384      // [4][32] int            128
#define SMEM_FL  48512
#define SMEM_BYTES (SMEM_FL * 4)   // 194048 B

__device__ __forceinline__ unsigned long long dup2(float a) {
    unsigned long long r;
    asm("mov.b64 %0, {%1, %1};" : "=l"(r) : "f"(a));
    return r;
}
__device__ __forceinline__ void ffma2(unsigned long long& d, unsigned long long a,
                                      unsigned long long b) {
    asm("fma.rn.f32x2 %0, %1, %2, %0;" : "+l"(d) : "l"(a), "l"(b));
}
__device__ __forceinline__ float2 unpk(unsigned long long v) {
    float lo, hi;
    asm("mov.b64 {%0, %1}, %2;" : "=f"(lo), "=f"(hi) : "l"(v));
    return make_float2(lo, hi);
}
__device__ __forceinline__ float gelu_f(float v) {
    return 0.5f * v * (1.0f + erff(v * 0.70710678118654752440f));
}
__device__ __forceinline__ void cp16(uint32_t dst, const void* src) {
    asm volatile("cp.async.cg.shared.global [%0], [%1], 16;" :: "r"(dst), "l"(src));
}
#define CP_COMMIT() asm volatile("cp.async.commit_group;" ::: "memory")
#define CP_WAIT0()  asm volatile("cp.async.wait_group 0;" ::: "memory")

// acc[2 k][8 c as 4 f32x2] += a[k] * b[8 c];  b pre-packed as 2x ulonglong2
__device__ __forceinline__ void rank1(unsigned long long (&acc)[2][4],
                                      float a0, float a1,
                                      ulonglong2 wA, ulonglong2 wB) {
    unsigned long long aa;
    aa = dup2(a0);
    ffma2(acc[0][0], aa, wA.x); ffma2(acc[0][1], aa, wA.y);
    ffma2(acc[0][2], aa, wB.x); ffma2(acc[0][3], aa, wB.y);
    aa = dup2(a1);
    ffma2(acc[1][0], aa, wA.x); ffma2(acc[1][1], aa, wA.y);
    ffma2(acc[1][2], aa, wB.x); ffma2(acc[1][3], aa, wB.y);
}

__global__ __launch_bounds__(512, 1)
void cfconv_kernel(const float* __restrict__ x,
                   const float* __restrict__ ef,
                   const int* __restrict__ eidx,
                   const float* __restrict__ W1,
                   const float* __restrict__ b1,
                   const float* __restrict__ W2,
                   const float* __restrict__ b2,
                   float* __restrict__ out)
{
    extern __shared__ float sm[];
    float* w1s  = sm + W1_OFF;
    float* w2s  = sm + W2_OFF;
    float* hs   = sm + HS_OFF;
    float* reds = sm + REDS_OFF;
    int*   idxs = (int*)(sm + IDX_OFF);
    const uint32_t efs_s32 = (uint32_t)__cvta_generic_to_shared(sm + EFS_OFF);

    const int tid = threadIdx.x;
    const int g   = tid >> 7;   // node within quad (0..3)
    const int l   = tid & 127;
    const int ti  = l >> 3;     // 0..15 -> k = 2ti, 2ti+1
    const int tj  = l & 7;      // cols {4tj..}, {32+4tj..}
    const int win = l >> 5;     // warp within node (0..3)

    // stage W1/W2 once per CTA
    {
        float4* w1d = (float4*)w1s;
        const float4* W14g = (const float4*)W1;
        for (int u = tid; u < 4800; u += 512) w1d[u] = W14g[u];
        float4* w2d = (float4*)w2s;
        const float4* W24g = (const float4*)W2;
        for (int u = tid; u < 1024; u += 512) w2d[u] = W24g[u];
    }

    const float4 c1A = ((const float4*)b1)[tj], c1B = ((const float4*)b1)[8 + tj];
    const float4 c2A = ((const float4*)b2)[tj], c2B = ((const float4*)b2)[8 + tj];

    const ulonglong2* w14p = (const ulonglong2*)w1s;
    const ulonglong2* w24p = (const ulonglong2*)w2s;
    const float4* efs4 = (const float4*)(sm + EFS_OFF);

    for (int q = blockIdx.x; q < NQUADS; q += gridDim.x) {
        const int nid0 = q << 2;

        if (tid < 128) {
            int nd = tid >> 5, k = tid & 31;
            idxs[nd * 32 + k] = (k < 30)
                ? (eidx[(nid0 + nd) * 30 + k] & 4095) : 0;
        }

        // prefetch chunk 0 -> buf 0 (1800 f4 = 4 nodes x 30 k x 15 f4)
        #pragma unroll 1
        for (int u = tid; u < 1800; u += 512) {
            int nd = u / 450;
            int r  = u - nd * 450;
            int k  = r / 15;
            int e4 = r - k * 15;
            uint32_t dst = efs_s32 + (uint32_t)(((nd * 32 + k) * 15 + e4) << 4);
            cp16(dst, ef + (long long)((nid0 + nd) * 30 + k) * 300 + e4 * 4);
        }
        CP_COMMIT();

        unsigned long long acc[2][4];
        #pragma unroll
        for (int a_ = 0; a_ < 2; ++a_)
            #pragma unroll
            for (int b_ = 0; b_ < 4; ++b_) acc[a_][b_] = 0ULL;

        // ---- GEMM1: E chunked 5 x 60, double-buffered cp.async ----
        #pragma unroll 1
        for (int ch = 0; ch < 5; ++ch) {
            CP_WAIT0();
            __syncthreads();
            if (ch < 4) {
                int buf = (ch + 1) & 1;
                #pragma unroll 1
                for (int u = tid; u < 1800; u += 512) {
                    int nd = u / 450;
                    int r  = u - nd * 450;
                    int k  = r / 15;
                    int e4 = r - k * 15;
                    uint32_t dst = efs_s32 +
                        (uint32_t)((buf * 1920 + (nd * 32 + k) * 15 + e4) << 4);
                    cp16(dst, ef + (long long)((nid0 + nd) * 30 + k) * 300
                                 + (ch + 1) * 60 + e4 * 4);
                }
                CP_COMMIT();
            }

            const float4* ea = efs4 + (ch & 1) * 1920 + (g * 32 + 2 * ti) * 15;
            int ew = (ch * 60) * 16 + tj;        // +64 per e4 step
            #pragma unroll 1
            for (int e4 = 0; e4 < 15; ++e4, ew += 64) {
                float4 a0 = ea[e4];
                float4 a1 = ea[e4 + 15];
                rank1(acc, a0.x, a1.x, w14p[ew],      w14p[ew + 8]);
                rank1(acc, a0.y, a1.y, w14p[ew + 16], w14p[ew + 24]);
                rank1(acc, a0.z, a1.z, w14p[ew + 32], w14p[ew + 40]);
                rank1(acc, a0.w, a1.w, w14p[ew + 48], w14p[ew + 56]);
            }
        }

        // ---- bias + exact gelu -> hs ----
        {
            float* hrow = hs + (g * 32 + 2 * ti) * 68;
            #pragma unroll
            for (int ik = 0; ik < 2; ++ik) {
                float2 u0 = unpk(acc[ik][0]);
                float2 u1 = unpk(acc[ik][1]);
                float2 u2 = unpk(acc[ik][2]);
                float2 u3 = unpk(acc[ik][3]);
                float4 vA = make_float4(gelu_f(u0.x + c1A.x), gelu_f(u0.y + c1A.y),
                                        gelu_f(u1.x + c1A.z), gelu_f(u1.y + c1A.w));
                float4 vB = make_float4(gelu_f(u2.x + c1B.x), gelu_f(u2.y + c1B.y),
                                        gelu_f(u3.x + c1B.z), gelu_f(u3.y + c1B.w));
                *(float4*)(hrow + ik * 68 + 4 * tj)      = vA;
                *(float4*)(hrow + ik * 68 + 32 + 4 * tj) = vB;
            }
        }
        __syncthreads();

        // ---- GEMM2: W = h @ W2 (both smem) ----
        #pragma unroll
        for (int a_ = 0; a_ < 2; ++a_)
            #pragma unroll
            for (int b_ = 0; b_ < 4; ++b_) acc[a_][b_] = 0ULL;
        {
            const float* hb = hs + (g * 32 + 2 * ti) * 68;
            #pragma unroll 4
            for (int cp = 0; cp < 64; ++cp) {
                float h0 = hb[cp];
                float h1 = hb[cp + 68];
                rank1(acc, h0, h1, w24p[cp * 16 + tj], w24p[cp * 16 + 8 + tj]);
            }
        }

        // ---- bias + gelu, gather x rows, per-thread partials over 2 k ----
        float pA[4] = {0.f, 0.f, 0.f, 0.f};
        float pB[4] = {0.f, 0.f, 0.f, 0.f};
        {
            const int bidx = nid0 >> 12;   // quads never straddle batch
            const float4* xb = (const float4*)x + (long long)bidx * 4096 * 16;
            #pragma unroll
            for (int ik = 0; ik < 2; ++ik) {
                int k = 2 * ti + ik;
                if (k < 30) {
                    float2 u0 = unpk(acc[ik][0]);
                    float2 u1 = unpk(acc[ik][1]);
                    float2 u2 = unpk(acc[ik][2]);
                    float2 u3 = unpk(acc[ik][3]);
                    int ix = idxs[g * 32 + k];
                    float4 xA = xb[ix * 16 + tj];
                    float4 xB = xb[ix * 16 + 8 + tj];
                    pA[0] += gelu_f(u0.x + c2A.x) * xA.x;
                    pA[1] += gelu_f(u0.y + c2A.y) * xA.y;
                    pA[2] += gelu_f(u1.x + c2A.z) * xA.z;
                    pA[3] += gelu_f(u1.y + c2A.w) * xA.w;
                    pB[0] += gelu_f(u2.x + c2B.x) * xB.x;
                    pB[1] += gelu_f(u2.y + c2B.y) * xB.y;
                    pB[2] += gelu_f(u3.x + c2B.z) * xB.z;
                    pB[3] += gelu_f(u3.y + c2B.w) * xB.w;
                }
            }
        }

        // ---- warp butterfly over ti low bits (lane bits 3,4) ----
        #pragma unroll
        for (int off = 8; off <= 16; off <<= 1) {
            #pragma unroll
            for (int j = 0; j < 4; ++j) {
                pA[j] += __shfl_xor_sync(0xFFFFFFFFu, pA[j], off);
                pB[j] += __shfl_xor_sync(0xFFFFFFFFu, pB[j], off);
            }
        }
        if ((l & 31) < 8) {
            float* rrow = reds + (g * 4 + win) * 64;
            *(float4*)(rrow + 4 * tj)      = make_float4(pA[0], pA[1], pA[2], pA[3]);
            *(float4*)(rrow + 32 + 4 * tj) = make_float4(pB[0], pB[1], pB[2], pB[3]);
        }
        __syncthreads();

        // ---- sum 4 warp rows -> out ----
        if (tid < 256) {
            int n2 = tid >> 6, c = tid & 63;
            float s = reds[(n2 * 4 + 0) * 64 + c] + reds[(n2 * 4 + 1) * 64 + c]
                    + reds[(n2 * 4 + 2) * 64 + c] + reds[(n2 * 4 + 3) * 64 + c];
            out[(long long)(nid0 + n2) * 64 + c] = s;
        }
        __syncthreads();   // protect smem reuse next iteration
    }
}

extern "C" void kernel_launch(void* const* d_in, const int* in_sizes, int n_in,
                              void* d_out, int out_size) {
    // Resolve inputs by element count (injective for this problem):
    //   ef: 147,456,000   x: 1,048,576   E_idx: 491,520 (int32)
    //   W1: 19,200        W2: 4,096      b1/b2: 64 (both zero vectors)
    const float* x  = 0;
    const float* ef = 0;
    const int*   ei = 0;
    const float* W1 = 0;
    const float* b1 = 0;
    const float* W2 = 0;
    const float* b2 = 0;
    for (int i = 0; i < n_in; ++i) {
        int sz = in_sizes[i];
        if      (sz == 147456000) ef = (const float*)d_in[i];
        else if (sz == 1048576)   x  = (const float*)d_in[i];
        else if (sz == 491520)    ei = (const int*)d_in[i];
        else if (sz == 19200)     W1 = (const float*)d_in[i];
        else if (sz == 4096)      W2 = (const float*)d_in[i];
        else if (sz == 64) { if (!b1) b1 = (const float*)d_in[i]; else b2 = (const float*)d_in[i]; }
    }
    if (!b2) b2 = b1;
    float* out = (float*)d_out;

    cudaFuncSetAttribute(cfconv_kernel,
                         cudaFuncAttributeMaxDynamicSharedMemorySize, SMEM_BYTES);
    cfconv_kernel<<<GRIDSZ, 512, SMEM_BYTES>>>(x, ef, ei, W1, b1, W2, b2, out);
}

// round 14
// speedup vs baseline: 1.3487x; 1.3487x over previous
#include <cuda_runtime.h>
#include <cstdint>

// CFConv fused: B=4, N=4096, K=30 (pad 32), C=64, E=300
// R14: R12's proven 4k x 8c tile (best LDS:FMA ratio) + 16 warps (4/SMSP) by
// processing 8 nodes per 512-thread CTA. ef smem chunk shrunk to 20 floats
// (15 double-buffered cp.async chunks) so everything fits in 208.9 KB smem.
// W1/W2 staged in smem, fma.rn.f32x2 core, W operands pre-packed ulonglong2.

#define NOCTS 2048
#define GRIDSZ 148

// smem layout (floats)
#define W1_OFF   0          // [300][64]            19200
#define W2_OFF   19200      // [64][64]              4096
#define EFS_OFF  23296      // 2 bufs x [8][32][20] 10240 (pitch 5 f4)
#define HS_OFF   33536      // [8][32][68]          17408
#define REDS_OFF 50944      // [16][64]              1024
#define IDX_OFF  51968      // [8][32] int            256
#define SMEM_FL  52224
#define SMEM_BYTES (SMEM_FL * 4)   // 208896 B

__device__ __forceinline__ unsigned long long dup2(float a) {
    unsigned long long r;
    asm("mov.b64 %0, {%1, %1};" : "=l"(r) : "f"(a));
    return r;
}
__device__ __forceinline__ void ffma2(unsigned long long& d, unsigned long long a,
                                      unsigned long long b) {
    asm("fma.rn.f32x2 %0, %1, %2, %0;" : "+l"(d) : "l"(a), "l"(b));
}
__device__ __forceinline__ float2 unpk(unsigned long long v) {
    float lo, hi;
    asm("mov.b64 {%0, %1}, %2;" : "=f"(lo), "=f"(hi) : "l"(v));
    return make_float2(lo, hi);
}
__device__ __forceinline__ float gelu_f(float v) {
    return 0.5f * v * (1.0f + erff(v * 0.70710678118654752440f));
}
__device__ __forceinline__ void cp16(uint32_t dst, const void* src) {
    asm volatile("cp.async.cg.shared.global [%0], [%1], 16;" :: "r"(dst), "l"(src));
}
#define CP_COMMIT() asm volatile("cp.async.commit_group;" ::: "memory")
#define CP_WAIT0()  asm volatile("cp.async.wait_group 0;" ::: "memory")

// acc[4 k][8 c as 4 f32x2] += a[k] * b[8 c]; b pre-packed as 2x ulonglong2
__device__ __forceinline__ void rank1(unsigned long long (&acc)[4][4],
                                      float a0, float a1, float a2, float a3,
                                      ulonglong2 wA, ulonglong2 wB) {
    unsigned long long aa;
    aa = dup2(a0);
    ffma2(acc[0][0], aa, wA.x); ffma2(acc[0][1], aa, wA.y);
    ffma2(acc[0][2], aa, wB.x); ffma2(acc[0][3], aa, wB.y);
    aa = dup2(a1);
    ffma2(acc[1][0], aa, wA.x); ffma2(acc[1][1], aa, wA.y);
    ffma2(acc[1][2], aa, wB.x); ffma2(acc[1][3], aa, wB.y);
    aa = dup2(a2);
    ffma2(acc[2][0], aa, wA.x); ffma2(acc[2][1], aa, wA.y);
    ffma2(acc[2][2], aa, wB.x); ffma2(acc[2][3], aa, wB.y);
    aa = dup2(a3);
    ffma2(acc[3][0], aa, wA.x); ffma2(acc[3][1], aa, wA.y);
    ffma2(acc[3][2], aa, wB.x); ffma2(acc[3][3], aa, wB.y);
}

__global__ __launch_bounds__(512, 1)
void cfconv_kernel(const float* __restrict__ x,
                   const float* __restrict__ ef,
                   const int* __restrict__ eidx,
                   const float* __restrict__ W1,
                   const float* __restrict__ b1,
                   const float* __restrict__ W2,
                   const float* __restrict__ b2,
                   float* __restrict__ out)
{
    extern __shared__ float sm[];
    float* w1s  = sm + W1_OFF;
    float* w2s  = sm + W2_OFF;
    float* hs   = sm + HS_OFF;
    float* reds = sm + REDS_OFF;
    int*   idxs = (int*)(sm + IDX_OFF);
    const uint32_t efs_s32 = (uint32_t)__cvta_generic_to_shared(sm + EFS_OFF);

    const int tid = threadIdx.x;
    const int g   = tid >> 6;   // node within octet (0..7)
    const int lt  = tid & 63;
    const int ti  = lt >> 3;    // k0 = 4*ti
    const int tj  = lt & 7;     // cols {4tj..}, {32+4tj..}
    const int win = lt >> 5;    // warp within node (0..1)

    // stage W1/W2 once per CTA
    {
        float4* w1d = (float4*)w1s;
        const float4* W14g = (const float4*)W1;
        for (int u = tid; u < 4800; u += 512) w1d[u] = W14g[u];
        float4* w2d = (float4*)w2s;
        const float4* W24g = (const float4*)W2;
        for (int u = tid; u < 1024; u += 512) w2d[u] = W24g[u];
    }

    const float4 c1A = ((const float4*)b1)[tj], c1B = ((const float4*)b1)[8 + tj];
    const float4 c2A = ((const float4*)b2)[tj], c2B = ((const float4*)b2)[8 + tj];

    const ulonglong2* w14p = (const ulonglong2*)w1s;
    const ulonglong2* w24p = (const ulonglong2*)w2s;
    const float4* efs4 = (const float4*)(sm + EFS_OFF);

    for (int q = blockIdx.x; q < NOCTS; q += gridDim.x) {
        const int nid0 = q << 3;

        if (tid < 256) {
            int nd = tid >> 5, k = tid & 31;
            idxs[nd * 32 + k] = (k < 30)
                ? (eidx[(nid0 + nd) * 30 + k] & 4095) : 0;
        }

        // prefetch chunk 0 -> buf 0 (1200 f4 = 8 nodes x 30 k x 5 f4)
        #pragma unroll 1
        for (int u = tid; u < 1200; u += 512) {
            int nd = u / 150;
            int r  = u - nd * 150;
            int k  = r / 5;
            int e4 = r - k * 5;
            uint32_t dst = efs_s32 + (uint32_t)(((nd * 32 + k) * 5 + e4) << 4);
            cp16(dst, ef + (long long)((nid0 + nd) * 30 + k) * 300 + e4 * 4);
        }
        CP_COMMIT();

        unsigned long long acc[4][4];
        #pragma unroll
        for (int a_ = 0; a_ < 4; ++a_)
            #pragma unroll
            for (int b_ = 0; b_ < 4; ++b_) acc[a_][b_] = 0ULL;

        // ---- GEMM1: E chunked 15 x 20, double-buffered cp.async ----
        #pragma unroll 1
        for (int ch = 0; ch < 15; ++ch) {
            CP_WAIT0();
            __syncthreads();   // buf[ch&1] full; prior reads of other buf done
            if (ch < 14) {
                int buf = (ch + 1) & 1;
                #pragma unroll 1
                for (int u = tid; u < 1200; u += 512) {
                    int nd = u / 150;
                    int r  = u - nd * 150;
                    int k  = r / 5;
                    int e4 = r - k * 5;
                    uint32_t dst = efs_s32 +
                        (uint32_t)((buf * 1280 + (nd * 32 + k) * 5 + e4) << 4);
                    cp16(dst, ef + (long long)((nid0 + nd) * 30 + k) * 300
                                 + (ch + 1) * 20 + e4 * 4);
                }
                CP_COMMIT();
            }

            const float4* ea = efs4 + (ch & 1) * 1280 + (g * 32 + 4 * ti) * 5;
            int ew = (ch * 20) * 16 + tj;        // +64 per e4 step
            #pragma unroll 1
            for (int e4 = 0; e4 < 5; ++e4, ew += 64) {
                float4 a0 = ea[e4];
                float4 a1 = ea[e4 + 5];
                float4 a2 = ea[e4 + 10];
                float4 a3 = ea[e4 + 15];
                rank1(acc, a0.x, a1.x, a2.x, a3.x, w14p[ew],      w14p[ew + 8]);
                rank1(acc, a0.y, a1.y, a2.y, a3.y, w14p[ew + 16], w14p[ew + 24]);
                rank1(acc, a0.z, a1.z, a2.z, a3.z, w14p[ew + 32], w14p[ew + 40]);
                rank1(acc, a0.w, a1.w, a2.w, a3.w, w14p[ew + 48], w14p[ew + 56]);
            }
        }

        // ---- bias + exact gelu -> hs ----
        {
            float* hrow = hs + (g * 32 + 4 * ti) * 68;
            #pragma unroll 1
            for (int ik = 0; ik < 4; ++ik) {
                float2 u0 = unpk(acc[ik][0]);
                float2 u1 = unpk(acc[ik][1]);
                float2 u2 = unpk(acc[ik][2]);
                float2 u3 = unpk(acc[ik][3]);
                float4 vA = make_float4(gelu_f(u0.x + c1A.x), gelu_f(u0.y + c1A.y),
                                        gelu_f(u1.x + c1A.z), gelu_f(u1.y + c1A.w));
                float4 vB = make_float4(gelu_f(u2.x + c1B.x), gelu_f(u2.y + c1B.y),
                                        gelu_f(u3.x + c1B.z), gelu_f(u3.y + c1B.w));
                *(float4*)(hrow + ik * 68 + 4 * tj)      = vA;
                *(float4*)(hrow + ik * 68 + 32 + 4 * tj) = vB;
            }
        }
        __syncthreads();

        // ---- GEMM2: W = h @ W2 (both smem) ----
        #pragma unroll
        for (int a_ = 0; a_ < 4; ++a_)
            #pragma unroll
            for (int b_ = 0; b_ < 4; ++b_) acc[a_][b_] = 0ULL;
        {
            const float* hb = hs + (g * 32 + 4 * ti) * 68;
            #pragma unroll 2
            for (int cp = 0; cp < 64; ++cp) {
                float h0 = hb[cp];
                float h1 = hb[cp + 68];
                float h2 = hb[cp + 136];
                float h3 = hb[cp + 204];
                ulonglong2 wA = w24p[cp * 16 + tj];
                ulonglong2 wB = w24p[cp * 16 + 8 + tj];
                unsigned long long aa;
                aa = dup2(h0);
                ffma2(acc[0][0], aa, wA.x); ffma2(acc[0][1], aa, wA.y);
                ffma2(acc[0][2], aa, wB.x); ffma2(acc[0][3], aa, wB.y);
                aa = dup2(h1);
                ffma2(acc[1][0], aa, wA.x); ffma2(acc[1][1], aa, wA.y);
                ffma2(acc[1][2], aa, wB.x); ffma2(acc[1][3], aa, wB.y);
                aa = dup2(h2);
                ffma2(acc[2][0], aa, wA.x); ffma2(acc[2][1], aa, wA.y);
                ffma2(acc[2][2], aa, wB.x); ffma2(acc[2][3], aa, wB.y);
                aa = dup2(h3);
                ffma2(acc[3][0], aa, wA.x); ffma2(acc[3][1], aa, wA.y);
                ffma2(acc[3][2], aa, wB.x); ffma2(acc[3][3], aa, wB.y);
            }
        }

        // ---- bias + gelu, gather x rows, per-thread partials over 4 k ----
        float pA[4] = {0.f, 0.f, 0.f, 0.f};
        float pB[4] = {0.f, 0.f, 0.f, 0.f};
        {
            const int bidx = nid0 >> 12;   // octets never straddle batch (8|4096)
            const float4* xb = (const float4*)x + (long long)bidx * 4096 * 16;
            #pragma unroll 1
            for (int ik = 0; ik < 4; ++ik) {
                int k = 4 * ti + ik;
                if (k < 30) {
                    float2 u0 = unpk(acc[ik][0]);
                    float2 u1 = unpk(acc[ik][1]);
                    float2 u2 = unpk(acc[ik][2]);
                    float2 u3 = unpk(acc[ik][3]);
                    int ix = idxs[g * 32 + k];
                    float4 xA = xb[ix * 16 + tj];
                    float4 xB = xb[ix * 16 + 8 + tj];
                    pA[0] += gelu_f(u0.x + c2A.x) * xA.x;
                    pA[1] += gelu_f(u0.y + c2A.y) * xA.y;
                    pA[2] += gelu_f(u1.x + c2A.z) * xA.z;
                    pA[3] += gelu_f(u1.y + c2A.w) * xA.w;
                    pB[0] += gelu_f(u2.x + c2B.x) * xB.x;
                    pB[1] += gelu_f(u2.y + c2B.y) * xB.y;
                    pB[2] += gelu_f(u3.x + c2B.z) * xB.z;
                    pB[3] += gelu_f(u3.y + c2B.w) * xB.w;
                }
            }
        }

        // ---- warp butterfly over ti low bits (lane bits 3,4) ----
        #pragma unroll
        for (int off = 8; off <= 16; off <<= 1) {
            #pragma unroll
            for (int j = 0; j < 4; ++j) {
                pA[j] += __shfl_xor_sync(0xFFFFFFFFu, pA[j], off);
                pB[j] += __shfl_xor_sync(0xFFFFFFFFu, pB[j], off);
            }
        }
        if ((lt & 31) < 8) {
            float* rrow = reds + (g * 2 + win) * 64;
            *(float4*)(rrow + 4 * tj)      = make_float4(pA[0], pA[1], pA[2], pA[3]);
            *(float4*)(rrow + 32 + 4 * tj) = make_float4(pB[0], pB[1], pB[2], pB[3]);
        }
        __syncthreads();

        // ---- sum 2 partial rows -> out (512 thr = 8 nodes x 64 cols) ----
        {
            int n2 = tid >> 6, c = tid & 63;
            float s = reds[(n2 * 2) * 64 + c] + reds[(n2 * 2 + 1) * 64 + c];
            out[(long long)(nid0 + n2) * 64 + c] = s;
        }
        __syncthreads();   // protect smem reuse next iteration
    }
}

extern "C" void kernel_launch(void* const* d_in, const int* in_sizes, int n_in,
                              void* d_out, int out_size) {
    // Resolve inputs by element count (injective for this problem):
    //   ef: 147,456,000   x: 1,048,576   E_idx: 491,520 (int32)
    //   W1: 19,200        W2: 4,096      b1/b2: 64 (both zero vectors)
    const float* x  = 0;
    const float* ef = 0;
    const int*   ei = 0;
    const float* W1 = 0;
    const float* b1 = 0;
    const float* W2 = 0;
    const float* b2 = 0;
    for (int i = 0; i < n_in; ++i) {
        int sz = in_sizes[i];
        if      (sz == 147456000) ef = (const float*)d_in[i];
        else if (sz == 1048576)   x  = (const float*)d_in[i];
        else if (sz == 491520)    ei = (const int*)d_in[i];
        else if (sz == 19200)     W1 = (const float*)d_in[i];
        else if (sz == 4096)      W2 = (const float*)d_in[i];
        else if (sz == 64) { if (!b1) b1 = (const float*)d_in[i]; else b2 = (const float*)d_in[i]; }
    }
    if (!b2) b2 = b1;
    float* out = (float*)d_out;

    cudaFuncSetAttribute(cfconv_kernel,
                         cudaFuncAttributeMaxDynamicSharedMemorySize, SMEM_BYTES);
    cfconv_kernel<<<GRIDSZ, 512, SMEM_BYTES>>>(x, ef, ei, W1, b1, W2, b2, out);
}

// round 16
// speedup vs baseline: 1.9514x; 1.4469x over previous
#include <cuda_runtime.h>
#include <cuda_bf16.h>
#include <cstdint>

// CFConv fused, tensor-core via mma.sync (HMMA bf16, works on plain sm_103 —
// tcgen05 needs the 'a' target the harness doesn't use).
// B=4, N=4096, K=30(pad32), C=64, E=300(pad304)
// 512 thr = 16 warps; per iter 8 nodes = M256. Warp w: rows 16w..16w+15.
// GEMM1: h = ef@W1, 19 ksteps x 8 ntiles x 3 bf16-splits (fp32-accurate).
// GEMM2: W = gelu(h)@W2 — GEMM1 D fragments reused as A fragments directly.
// Epilogue: gather x rows, reduce over k.

#define NOCTS 2048
#define GRIDSZ 148

// smem word offsets
#define W1HI_OFF 0          // [152][72] u32  10944
#define W1LO_OFF 10944
#define W2HI_OFF 21888      // [32][72] u32    2304
#define W2LO_OFF 24192
#define B1_OFF   26496      // 64 f32
#define B2_OFF   26560
#define IDX_OFF  26624      // 256 int
#define REDS_OFF 26880      // [16][64] f32
#define SMEM_WORDS 27904
#define SMEM_BYTES (SMEM_WORDS * 4)   // 111616

__device__ __forceinline__ float gelu_f(float v) {
    return 0.5f * v * (1.0f + erff(v * 0.70710678118654752440f));
}
__device__ __forceinline__ void split2(float v0, float v1,
                                       uint32_t& hi, uint32_t& lo) {
    __nv_bfloat162 hb = __floats2bfloat162_rn(v0, v1);
    uint32_t h = *reinterpret_cast<uint32_t*>(&hb);
    float h0 = __uint_as_float(h << 16);
    float h1 = __uint_as_float(h & 0xFFFF0000u);
    __nv_bfloat162 lb = __floats2bfloat162_rn(v0 - h0, v1 - h1);
    hi = h;
    lo = *reinterpret_cast<uint32_t*>(&lb);
}
__device__ __forceinline__ void mma_bf16(float (&d)[4],
                                         uint32_t a0, uint32_t a1,
                                         uint32_t a2, uint32_t a3,
                                         uint32_t b0, uint32_t b1) {
    asm volatile(
        "mma.sync.aligned.m16n8k16.row.col.f32.bf16.bf16.f32 "
        "{%0,%1,%2,%3}, {%4,%5,%6,%7}, {%8,%9}, {%0,%1,%2,%3};"
        : "+f"(d[0]), "+f"(d[1]), "+f"(d[2]), "+f"(d[3])
        : "r"(a0), "r"(a1), "r"(a2), "r"(a3), "r"(b0), "r"(b1));
}

__global__ __launch_bounds__(512, 1)
void cfconv_kernel(const float* __restrict__ x,
                   const float* __restrict__ ef,
                   const int* __restrict__ eidx,
                   const float* __restrict__ W1,
                   const float* __restrict__ b1,
                   const float* __restrict__ W2,
                   const float* __restrict__ b2,
                   float* __restrict__ out)
{
    extern __shared__ float sm[];
    uint32_t* w1hi = (uint32_t*)(sm + W1HI_OFF);
    uint32_t* w1lo = (uint32_t*)(sm + W1LO_OFF);
    uint32_t* w2hi = (uint32_t*)(sm + W2HI_OFF);
    uint32_t* w2lo = (uint32_t*)(sm + W2LO_OFF);
    float* b1s  = sm + B1_OFF;
    float* b2s  = sm + B2_OFF;
    int*   idxs = (int*)(sm + IDX_OFF);
    float* reds = sm + REDS_OFF;

    const int tid  = threadIdx.x;
    const int w    = tid >> 5;
    const int lane = tid & 31;
    const int lr   = lane >> 2;   // 0..7 (row slot / n-col slot)
    const int lc   = lane & 3;    // 0..3 (col-pair slot / k slot)

    // ---- stage W1/W2 bf16 hi/lo, k-pair packed, pitch 72 (conflict-free) ----
    #pragma unroll 1
    for (int u = tid; u < 9728; u += 512) {       // 152 kp x 64 n
        int kp = u >> 6, n = u & 63;
        int e0 = 2 * kp;
        float v0 = (e0     < 300) ? W1[e0 * 64 + n]       : 0.f;
        float v1 = (e0 + 1 < 300) ? W1[(e0 + 1) * 64 + n] : 0.f;
        uint32_t hi, lo;
        split2(v0, v1, hi, lo);
        w1hi[kp * 72 + n] = hi;
        w1lo[kp * 72 + n] = lo;
    }
    #pragma unroll 1
    for (int u = tid; u < 2048; u += 512) {       // 32 kp x 64 n
        int kp = u >> 6, n = u & 63;
        float v0 = W2[(2 * kp) * 64 + n];
        float v1 = W2[(2 * kp + 1) * 64 + n];
        uint32_t hi, lo;
        split2(v0, v1, hi, lo);
        w2hi[kp * 72 + n] = hi;
        w2lo[kp * 72 + n] = lo;
    }
    if (tid < 64) b1s[tid] = b1[tid];
    else if (tid < 128) b2s[tid - 64] = b2[tid - 64];
    __syncthreads();

    const int g   = w >> 1;                 // node within octet (0..7)
    const int kk0 = (w & 1) * 16 + lr;      // always < 24
    const int kk1 = kk0 + 8;
    const bool v1ok = (kk1 < 30);

    for (int q = blockIdx.x; q < NOCTS; q += gridDim.x) {
        const int nid0 = q << 3;

        if (tid < 256) {
            int nd = tid >> 5, k = tid & 31;
            idxs[tid] = (k < 30) ? (eidx[(nid0 + nd) * 30 + k] & 4095) : 0;
        }
        __syncthreads();

        const float* rowp0 = ef + (long long)((nid0 + g) * 30 + kk0) * 300;
        const float* rowp1 = ef + (long long)((nid0 + g) * 30 + (v1ok ? kk1 : kk0)) * 300;

        // ---- GEMM1: h = ef @ W1 (19 ksteps, 3 splits) ----
        float acc[8][4];
        #pragma unroll
        for (int nt = 0; nt < 8; ++nt)
            #pragma unroll
            for (int j = 0; j < 4; ++j) acc[nt][j] = 0.f;

        #pragma unroll 1
        for (int ks = 0; ks < 19; ++ks) {
            int cb = ks * 16 + 2 * lc;
            float2 z = make_float2(0.f, 0.f);
            float2 p00 = (cb < 300)            ? *(const float2*)(rowp0 + cb)     : z;
            float2 p10 = (v1ok && cb < 300)    ? *(const float2*)(rowp1 + cb)     : z;
            float2 p01 = (cb + 8 < 300)          ? *(const float2*)(rowp0 + cb + 8) : z;
            float2 p11 = (v1ok && cb + 8 < 300)  ? *(const float2*)(rowp1 + cb + 8) : z;
            uint32_t ah0, ah1, ah2, ah3, al0, al1, al2, al3;
            split2(p00.x, p00.y, ah0, al0);
            split2(p10.x, p10.y, ah1, al1);
            split2(p01.x, p01.y, ah2, al2);
            split2(p11.x, p11.y, ah3, al3);
            int kb0 = (8 * ks + lc) * 72 + lr;
            int kb1 = kb0 + 4 * 72;
            #pragma unroll
            for (int nt = 0; nt < 8; ++nt) {
                uint32_t bh0 = w1hi[kb0 + 8 * nt];
                uint32_t bh1 = w1hi[kb1 + 8 * nt];
                uint32_t bl0 = w1lo[kb0 + 8 * nt];
                uint32_t bl1 = w1lo[kb1 + 8 * nt];
                mma_bf16(acc[nt], ah0, ah1, ah2, ah3, bh0, bh1);
                mma_bf16(acc[nt], ah0, ah1, ah2, ah3, bl0, bl1);
                mma_bf16(acc[nt], al0, al1, al2, al3, bh0, bh1);
            }
        }

        // ---- h = gelu(acc + b1) -> bf16 fragment pairs (regs only) ----
        uint32_t hhi[8][2], hlo[8][2];
        #pragma unroll
        for (int nt = 0; nt < 8; ++nt) {
            int c0 = 8 * nt + 2 * lc;
            float2 bb = *(const float2*)(b1s + c0);
            float f0 = gelu_f(acc[nt][0] + bb.x);
            float f1 = gelu_f(acc[nt][1] + bb.y);
            float f2 = gelu_f(acc[nt][2] + bb.x);
            float f3 = gelu_f(acc[nt][3] + bb.y);
            split2(f0, f1, hhi[nt][0], hlo[nt][0]);
            split2(f2, f3, hhi[nt][1], hlo[nt][1]);
        }

        // ---- GEMM2: W = h @ W2 (4 ksteps, 3 splits) ----
        float acc2[8][4];
        #pragma unroll
        for (int nt = 0; nt < 8; ++nt)
            #pragma unroll
            for (int j = 0; j < 4; ++j) acc2[nt][j] = 0.f;

        #pragma unroll
        for (int ks = 0; ks < 4; ++ks) {
            uint32_t ah0 = hhi[2 * ks][0],     ah1 = hhi[2 * ks][1];
            uint32_t ah2 = hhi[2 * ks + 1][0], ah3 = hhi[2 * ks + 1][1];
            uint32_t al0 = hlo[2 * ks][0],     al1 = hlo[2 * ks][1];
            uint32_t al2 = hlo[2 * ks + 1][0], al3 = hlo[2 * ks + 1][1];
            int kb0 = (8 * ks + lc) * 72 + lr;
            int kb1 = kb0 + 4 * 72;
            #pragma unroll
            for (int nt = 0; nt < 8; ++nt) {
                uint32_t bh0 = w2hi[kb0 + 8 * nt];
                uint32_t bh1 = w2hi[kb1 + 8 * nt];
                uint32_t bl0 = w2lo[kb0 + 8 * nt];
                uint32_t bl1 = w2lo[kb1 + 8 * nt];
                mma_bf16(acc2[nt], ah0, ah1, ah2, ah3, bh0, bh1);
                mma_bf16(acc2[nt], ah0, ah1, ah2, ah3, bl0, bl1);
                mma_bf16(acc2[nt], al0, al1, al2, al3, bh0, bh1);
            }
        }

        // ---- epilogue: gelu(+b2), gather x, reduce over rows ----
        {
            const int bidx = nid0 >> 12;
            const float* xb = x + (long long)bidx * 4096 * 64;
            int ix0 = idxs[g * 32 + kk0];
            int ix1 = idxs[g * 32 + (v1ok ? kk1 : kk0)];
            float2 p[8];
            #pragma unroll
            for (int nt = 0; nt < 8; ++nt) {
                int c0 = 8 * nt + 2 * lc;
                float2 bb = *(const float2*)(b2s + c0);
                float w00 = gelu_f(acc2[nt][0] + bb.x);
                float w01 = gelu_f(acc2[nt][1] + bb.y);
                float w10 = gelu_f(acc2[nt][2] + bb.x);
                float w11 = gelu_f(acc2[nt][3] + bb.y);
                float2 x0 = *(const float2*)(xb + ix0 * 64 + c0);
                p[nt].x = w00 * x0.x;
                p[nt].y = w01 * x0.y;
                if (v1ok) {
                    float2 x1 = *(const float2*)(xb + ix1 * 64 + c0);
                    p[nt].x += w10 * x1.x;
                    p[nt].y += w11 * x1.y;
                }
            }
            // reduce over the 8 row-slots (lane bits 2..4)
            #pragma unroll
            for (int off = 4; off <= 16; off <<= 1) {
                #pragma unroll
                for (int nt = 0; nt < 8; ++nt) {
                    p[nt].x += __shfl_xor_sync(0xFFFFFFFFu, p[nt].x, off);
                    p[nt].y += __shfl_xor_sync(0xFFFFFFFFu, p[nt].y, off);
                }
            }
            if (lane < 4) {   // lr==0 lanes: lc = lane
                #pragma unroll
                for (int nt = 0; nt < 8; ++nt)
                    *(float2*)(reds + w * 64 + 8 * nt + 2 * lane) = p[nt];
            }
        }
        __syncthreads();

        {
            int n2 = tid >> 6, c = tid & 63;
            out[(long long)(nid0 + n2) * 64 + c] =
                reds[(2 * n2) * 64 + c] + reds[(2 * n2 + 1) * 64 + c];
        }
        __syncthreads();
    }
}

extern "C" void kernel_launch(void* const* d_in, const int* in_sizes, int n_in,
                              void* d_out, int out_size) {
    // Resolve inputs by element count (injective for this problem):
    //   ef: 147,456,000   x: 1,048,576   E_idx: 491,520 (int32)
    //   W1: 19,200        W2: 4,096      b1/b2: 64 (both zero vectors)
    const float* x  = 0;
    const float* ef = 0;
    const int*   ei = 0;
    const float* W1 = 0;
    const float* b1 = 0;
    const float* W2 = 0;
    const float* b2 = 0;
    for (int i = 0; i < n_in; ++i) {
        int sz = in_sizes[i];
        if      (sz == 147456000) ef = (const float*)d_in[i];
        else if (sz == 1048576)   x  = (const float*)d_in[i];
        else if (sz == 491520)    ei = (const int*)d_in[i];
        else if (sz == 19200)     W1 = (const float*)d_in[i];
        else if (sz == 4096)      W2 = (const float*)d_in[i];
        else if (sz == 64) { if (!b1) b1 = (const float*)d_in[i]; else b2 = (const float*)d_in[i]; }
    }
    if (!b2) b2 = b1;
    float* out = (float*)d_out;

    cudaFuncSetAttribute(cfconv_kernel,
                         cudaFuncAttributeMaxDynamicSharedMemorySize, SMEM_BYTES);
    cfconv_kernel<<<GRIDSZ, 512, SMEM_BYTES>>>(x, ef, ei, W1, b1, W2, b2, out);
}

// round 17
// speedup vs baseline: 3.1088x; 1.5931x over previous
#include <cuda_runtime.h>
#include <cuda_bf16.h>
#include <cstdint>

// CFConv fused, tensor-core mma.sync bf16 3-split (fp32-accurate), sm_103.
// R17: software-pipelined ef loads (1 k-step ahead, kills the exposed
// DRAM-latency chain that held issue at 27%), __ldcs streaming hint on ef,
// x-gather loads hoisted ahead of the gelu math in the epilogue.
// 512 thr = 16 warps; 8 nodes (M=256) per iter; warp w: rows 16w..16w+15.

#define NOCTS 2048
#define GRIDSZ 148

// smem word offsets
#define W1HI_OFF 0          // [152][72] u32  10944
#define W1LO_OFF 10944
#define W2HI_OFF 21888      // [32][72] u32    2304
#define W2LO_OFF 24192
#define B1_OFF   26496      // 64 f32
#define B2_OFF   26560
#define IDX_OFF  26624      // 256 int
#define REDS_OFF 26880      // [16][64] f32
#define SMEM_WORDS 27904
#define SMEM_BYTES (SMEM_WORDS * 4)   // 111616

__device__ __forceinline__ float gelu_f(float v) {
    return 0.5f * v * (1.0f + erff(v * 0.70710678118654752440f));
}
__device__ __forceinline__ void split2(float v0, float v1,
                                       uint32_t& hi, uint32_t& lo) {
    __nv_bfloat162 hb = __floats2bfloat162_rn(v0, v1);
    uint32_t h = *reinterpret_cast<uint32_t*>(&hb);
    float h0 = __uint_as_float(h << 16);
    float h1 = __uint_as_float(h & 0xFFFF0000u);
    __nv_bfloat162 lb = __floats2bfloat162_rn(v0 - h0, v1 - h1);
    hi = h;
    lo = *reinterpret_cast<uint32_t*>(&lb);
}
__device__ __forceinline__ void mma_bf16(float (&d)[4],
                                         uint32_t a0, uint32_t a1,
                                         uint32_t a2, uint32_t a3,
                                         uint32_t b0, uint32_t b1) {
    asm volatile(
        "mma.sync.aligned.m16n8k16.row.col.f32.bf16.bf16.f32 "
        "{%0,%1,%2,%3}, {%4,%5,%6,%7}, {%8,%9}, {%0,%1,%2,%3};"
        : "+f"(d[0]), "+f"(d[1]), "+f"(d[2]), "+f"(d[3])
        : "r"(a0), "r"(a1), "r"(a2), "r"(a3), "r"(b0), "r"(b1));
}

__global__ __launch_bounds__(512, 1)
void cfconv_kernel(const float* __restrict__ x,
                   const float* __restrict__ ef,
                   const int* __restrict__ eidx,
                   const float* __restrict__ W1,
                   const float* __restrict__ b1,
                   const float* __restrict__ W2,
                   const float* __restrict__ b2,
                   float* __restrict__ out)
{
    extern __shared__ float sm[];
    uint32_t* w1hi = (uint32_t*)(sm + W1HI_OFF);
    uint32_t* w1lo = (uint32_t*)(sm + W1LO_OFF);
    uint32_t* w2hi = (uint32_t*)(sm + W2HI_OFF);
    uint32_t* w2lo = (uint32_t*)(sm + W2LO_OFF);
    float* b1s  = sm + B1_OFF;
    float* b2s  = sm + B2_OFF;
    int*   idxs = (int*)(sm + IDX_OFF);
    float* reds = sm + REDS_OFF;

    const int tid  = threadIdx.x;
    const int w    = tid >> 5;
    const int lane = tid & 31;
    const int lr   = lane >> 2;   // 0..7 (row slot / n-col slot)
    const int lc   = lane & 3;    // 0..3 (col-pair slot / k slot)

    // ---- stage W1/W2 bf16 hi/lo, k-pair packed, pitch 72 (conflict-free) ----
    #pragma unroll 1
    for (int u = tid; u < 9728; u += 512) {       // 152 kp x 64 n
        int kp = u >> 6, n = u & 63;
        int e0 = 2 * kp;
        float v0 = (e0     < 300) ? W1[e0 * 64 + n]       : 0.f;
        float v1 = (e0 + 1 < 300) ? W1[(e0 + 1) * 64 + n] : 0.f;
        uint32_t hi, lo;
        split2(v0, v1, hi, lo);
        w1hi[kp * 72 + n] = hi;
        w1lo[kp * 72 + n] = lo;
    }
    #pragma unroll 1
    for (int u = tid; u < 2048; u += 512) {       // 32 kp x 64 n
        int kp = u >> 6, n = u & 63;
        float v0 = W2[(2 * kp) * 64 + n];
        float v1 = W2[(2 * kp + 1) * 64 + n];
        uint32_t hi, lo;
        split2(v0, v1, hi, lo);
        w2hi[kp * 72 + n] = hi;
        w2lo[kp * 72 + n] = lo;
    }
    if (tid < 64) b1s[tid] = b1[tid];
    else if (tid < 128) b2s[tid - 64] = b2[tid - 64];
    __syncthreads();

    const int g   = w >> 1;                 // node within octet (0..7)
    const int kk0 = (w & 1) * 16 + lr;      // always < 24
    const int kk1 = kk0 + 8;
    const bool v1ok = (kk1 < 30);
    const float2 z2 = make_float2(0.f, 0.f);

    for (int q = blockIdx.x; q < NOCTS; q += gridDim.x) {
        const int nid0 = q << 3;

        if (tid < 256) {
            int nd = tid >> 5, k = tid & 31;
            idxs[tid] = (k < 30) ? (eidx[(nid0 + nd) * 30 + k] & 4095) : 0;
        }
        __syncthreads();

        const float* rowp0 = ef + (long long)((nid0 + g) * 30 + kk0) * 300;
        const float* rowp1 = ef + (long long)((nid0 + g) * 30 + (v1ok ? kk1 : kk0)) * 300;

        // ---- GEMM1: h = ef @ W1 (19 ksteps, 3 splits, 1-deep load pipeline) ----
        float acc[8][4];
        #pragma unroll
        for (int nt = 0; nt < 8; ++nt)
            #pragma unroll
            for (int j = 0; j < 4; ++j) acc[nt][j] = 0.f;

        float2 c00, c10, c01, c11;
        {
            int cb = 2 * lc;
            c00 = __ldcs((const float2*)(rowp0 + cb));
            c01 = __ldcs((const float2*)(rowp0 + cb + 8));
            c10 = v1ok ? __ldcs((const float2*)(rowp1 + cb))     : z2;
            c11 = v1ok ? __ldcs((const float2*)(rowp1 + cb + 8)) : z2;
        }

        #pragma unroll 1
        for (int ks = 0; ks < 19; ++ks) {
            // prefetch next k-step while this one computes
            float2 n00 = z2, n10 = z2, n01 = z2, n11 = z2;
            if (ks < 18) {
                int cb = (ks + 1) * 16 + 2 * lc;     // <= 294, p00 always valid
                bool ok1 = (cb + 8) < 300;
                n00 = __ldcs((const float2*)(rowp0 + cb));
                if (ok1) n01 = __ldcs((const float2*)(rowp0 + cb + 8));
                if (v1ok) {
                    n10 = __ldcs((const float2*)(rowp1 + cb));
                    if (ok1) n11 = __ldcs((const float2*)(rowp1 + cb + 8));
                }
            }

            uint32_t ah0, ah1, ah2, ah3, al0, al1, al2, al3;
            split2(c00.x, c00.y, ah0, al0);
            split2(c10.x, c10.y, ah1, al1);
            split2(c01.x, c01.y, ah2, al2);
            split2(c11.x, c11.y, ah3, al3);
            int kb0 = (8 * ks + lc) * 72 + lr;
            int kb1 = kb0 + 4 * 72;
            #pragma unroll
            for (int nt = 0; nt < 8; ++nt) {
                uint32_t bh0 = w1hi[kb0 + 8 * nt];
                uint32_t bh1 = w1hi[kb1 + 8 * nt];
                uint32_t bl0 = w1lo[kb0 + 8 * nt];
                uint32_t bl1 = w1lo[kb1 + 8 * nt];
                mma_bf16(acc[nt], ah0, ah1, ah2, ah3, bh0, bh1);
                mma_bf16(acc[nt], ah0, ah1, ah2, ah3, bl0, bl1);
                mma_bf16(acc[nt], al0, al1, al2, al3, bh0, bh1);
            }
            c00 = n00; c10 = n10; c01 = n01; c11 = n11;
        }

        // ---- h = gelu(acc + b1) -> bf16 fragment pairs (regs only) ----
        uint32_t hhi[8][2], hlo[8][2];
        #pragma unroll
        for (int nt = 0; nt < 8; ++nt) {
            int c0 = 8 * nt + 2 * lc;
            float2 bb = *(const float2*)(b1s + c0);
            float f0 = gelu_f(acc[nt][0] + bb.x);
            float f1 = gelu_f(acc[nt][1] + bb.y);
            float f2 = gelu_f(acc[nt][2] + bb.x);
            float f3 = gelu_f(acc[nt][3] + bb.y);
            split2(f0, f1, hhi[nt][0], hlo[nt][0]);
            split2(f2, f3, hhi[nt][1], hlo[nt][1]);
        }

        // ---- GEMM2: W = h @ W2 (4 ksteps, 3 splits) ----
        float acc2[8][4];
        #pragma unroll
        for (int nt = 0; nt < 8; ++nt)
            #pragma unroll
            for (int j = 0; j < 4; ++j) acc2[nt][j] = 0.f;

        #pragma unroll
        for (int ks = 0; ks < 4; ++ks) {
            uint32_t ah0 = hhi[2 * ks][0],     ah1 = hhi[2 * ks][1];
            uint32_t ah2 = hhi[2 * ks + 1][0], ah3 = hhi[2 * ks + 1][1];
            uint32_t al0 = hlo[2 * ks][0],     al1 = hlo[2 * ks][1];
            uint32_t al2 = hlo[2 * ks + 1][0], al3 = hlo[2 * ks + 1][1];
            int kb0 = (8 * ks + lc) * 72 + lr;
            int kb1 = kb0 + 4 * 72;
            #pragma unroll
            for (int nt = 0; nt < 8; ++nt) {
                uint32_t bh0 = w2hi[kb0 + 8 * nt];
                uint32_t bh1 = w2hi[kb1 + 8 * nt];
                uint32_t bl0 = w2lo[kb0 + 8 * nt];
                uint32_t bl1 = w2lo[kb1 + 8 * nt];
                mma_bf16(acc2[nt], ah0, ah1, ah2, ah3, bh0, bh1);
                mma_bf16(acc2[nt], ah0, ah1, ah2, ah3, bl0, bl1);
                mma_bf16(acc2[nt], al0, al1, al2, al3, bh0, bh1);
            }
        }

        // ---- epilogue: x loads first (hide L2 latency under gelu math) ----
        {
            const int bidx = nid0 >> 12;
            const float* xb = x + (long long)bidx * 4096 * 64;
            int ix0 = idxs[g * 32 + kk0];
            int ix1 = idxs[g * 32 + (v1ok ? kk1 : kk0)];
            float2 x0r[8], x1r[8];
            #pragma unroll
            for (int nt = 0; nt < 8; ++nt) {
                int c0 = 8 * nt + 2 * lc;
                x0r[nt] = *(const float2*)(xb + ix0 * 64 + c0);
                x1r[nt] = v1ok ? *(const float2*)(xb + ix1 * 64 + c0) : z2;
            }
            float2 p[8];
            #pragma unroll
            for (int nt = 0; nt < 8; ++nt) {
                int c0 = 8 * nt + 2 * lc;
                float2 bb = *(const float2*)(b2s + c0);
                float w00 = gelu_f(acc2[nt][0] + bb.x);
                float w01 = gelu_f(acc2[nt][1] + bb.y);
                float w10 = gelu_f(acc2[nt][2] + bb.x);
                float w11 = gelu_f(acc2[nt][3] + bb.y);
                p[nt].x = w00 * x0r[nt].x + w10 * x1r[nt].x;
                p[nt].y = w01 * x0r[nt].y + w11 * x1r[nt].y;
            }
            // reduce over the 8 row-slots (lane bits 2..4)
            #pragma unroll
            for (int off = 4; off <= 16; off <<= 1) {
                #pragma unroll
                for (int nt = 0; nt < 8; ++nt) {
                    p[nt].x += __shfl_xor_sync(0xFFFFFFFFu, p[nt].x, off);
                    p[nt].y += __shfl_xor_sync(0xFFFFFFFFu, p[nt].y, off);
                }
            }
            if (lane < 4) {   // lr==0 lanes: lc = lane
                #pragma unroll
                for (int nt = 0; nt < 8; ++nt)
                    *(float2*)(reds + w * 64 + 8 * nt + 2 * lane) = p[nt];
            }
        }
        __syncthreads();

        {
            int n2 = tid >> 6, c = tid & 63;
            out[(long long)(nid0 + n2) * 64 + c] =
                reds[(2 * n2) * 64 + c] + reds[(2 * n2 + 1) * 64 + c];
        }
        __syncthreads();
    }
}

extern "C" void kernel_launch(void* const* d_in, const int* in_sizes, int n_in,
                              void* d_out, int out_size) {
    // Resolve inputs by element count (injective for this problem):
    //   ef: 147,456,000   x: 1,048,576   E_idx: 491,520 (int32)
    //   W1: 19,200        W2: 4,096      b1/b2: 64 (both zero vectors)
    const float* x  = 0;
    const float* ef = 0;
    const int*   ei = 0;
    const float* W1 = 0;
    const float* b1 = 0;
    const float* W2 = 0;
    const float* b2 = 0;
    for (int i = 0; i < n_in; ++i) {
        int sz = in_sizes[i];
        if      (sz == 147456000) ef = (const float*)d_in[i];
        else if (sz == 1048576)   x  = (const float*)d_in[i];
        else if (sz == 491520)    ei = (const int*)d_in[i];
        else if (sz == 19200)     W1 = (const float*)d_in[i];
        else if (sz == 4096)      W2 = (const float*)d_in[i];
        else if (sz == 64) { if (!b1) b1 = (const float*)d_in[i]; else b2 = (const float*)d_in[i]; }
    }
    if (!b2) b2 = b1;
    float* out = (float*)d_out;

    cudaFuncSetAttribute(cfconv_kernel,
                         cudaFuncAttributeMaxDynamicSharedMemorySize, SMEM_BYTES);
    cfconv_kernel<<<GRIDSZ, 512, SMEM_BYTES>>>(x, ef, ei, W1, b1, W2, b2, out);
}